// round 8
// baseline (speedup 1.0000x reference)
#include <cuda_runtime.h>
#include <cuda_fp16.h>
#include <cstdint>

#define IN_C    256
#define HID     16
#define HEADS   8
#define F1      128     // HEADS*HID
#define OUT_C   32
#define SLOPE   0.2f
#define N_MAX   50048
#define E_MAX   851968  // E + N headroom

// ---------------- scratch (device globals; no allocation allowed) ----------
__device__ int2     g_edges  [E_MAX];
__device__ int      g_csr_src[E_MAX];
__device__ int      g_cnt    [N_MAX];        // zero at entry; scan re-zeroes
__device__ int      g_rowptr [N_MAX + 1];
__device__ int      g_cursor [N_MAX];
__device__ int      g_bsum   [64];
__device__ int      g_ctr1;                  // zero at entry; scan resets
__device__ int      g_ctr2;
__device__ int      g_done;
__device__ __half   g_h1h [(size_t)N_MAX * F1];
__device__ float    g_als1[(size_t)N_MAX * HEADS];
__device__ float    g_ald1[(size_t)N_MAX * HEADS];
__device__ __half   g_h2h [(size_t)N_MAX * OUT_C];
__device__ float    g_als2[N_MAX];
__device__ float    g_ald2[N_MAX];

__device__ __forceinline__ float lrelu(float v) { return v > 0.f ? v : SLOPE * v; }

// --------------- edge decode + degree histogram (inline dtype detect) --------
__global__ void prep_kernel(const void* ei, int E, int Et) {
    __shared__ int s_is64;
    if (threadIdx.x == 0) {
        const int* p = (const int*)ei;
        int all0 = 1;
#pragma unroll
        for (int k = 1; k < 64; k += 2) all0 &= (p[k] == 0);
        s_is64 = all0;
    }
    __syncthreads();
    int e = blockIdx.x * blockDim.x + threadIdx.x;
    if (e >= Et) return;
    int s, d;
    if (e < E) {
        if (s_is64) {
            const long long* p = (const long long*)ei;
            s = (int)__ldg(p + e); d = (int)__ldg(p + (size_t)E + e);
        } else {
            const int* p = (const int*)ei;
            s = __ldg(p + e); d = __ldg(p + (size_t)E + e);
        }
    } else {
        s = d = e - E;
    }
    g_edges[e] = make_int2(s, d);
    atomicAdd(&g_cnt[d], 1);
}

// --------------- full scan in one kernel (co-resident spin release) ----------
// grid = ceil(n/1024) <= 49 blocks -> all co-resident on 148 SMs; spin is safe.
__global__ __launch_bounds__(1024) void scan_kernel(int n, int nb, int Et) {
    __shared__ int sm[1024];
    __shared__ int amLast;
    int tid = threadIdx.x;
    int i = blockIdx.x * 1024 + tid;
    int v = (i < n) ? g_cnt[i] : 0;
    sm[tid] = v;
    __syncthreads();
    for (int off = 1; off < 1024; off <<= 1) {
        int t = (tid >= off) ? sm[tid - off] : 0;
        __syncthreads();
        sm[tid] += t;
        __syncthreads();
    }
    if (tid == 1023) g_bsum[blockIdx.x] = sm[1023];
    __threadfence();
    if (tid == 0) {
        int t = atomicAdd(&g_ctr1, 1);
        amLast = (t == (int)gridDim.x - 1);
    }
    __syncthreads();
    if (amLast && tid < 32) {
        int lane = tid;
        int a = (2 * lane < nb) ? g_bsum[2 * lane] : 0;
        int b = (2 * lane + 1 < nb) ? g_bsum[2 * lane + 1] : 0;
        int p = a + b;
#pragma unroll
        for (int off = 1; off < 32; off <<= 1) {
            int t = __shfl_up_sync(0xffffffffu, p, off);
            if (lane >= off) p += t;
        }
        int excl = p - (a + b);
        g_bsum[2 * lane]     = excl + a;
        g_bsum[2 * lane + 1] = excl + a + b;
        __threadfence();
        if (lane == 0) atomicExch(&g_done, 1);
    }
    // spin until block sums are finalized
    if (tid == 0) {
        while (atomicAdd(&g_done, 0) == 0) { }
    }
    __syncthreads();
    __threadfence();
    // finalize rowptr/cursor, zero cnt
    if (blockIdx.x == 0 && tid == 0) g_rowptr[n] = Et;
    if (i < n) {
        int pre = blockIdx.x ? __ldcg(&g_bsum[blockIdx.x - 1]) : 0;
        int start = sm[tid] - v + pre;
        g_rowptr[i] = start;
        g_cursor[i] = start;
        g_cnt[i] = 0;                            // restore precondition for replay
    }
    __threadfence();
    if (tid == 0) {
        int t2 = atomicAdd(&g_ctr2, 1);
        if (t2 == (int)gridDim.x - 1) {          // last to exit resets flags
            g_ctr1 = 0; g_ctr2 = 0; g_done = 0;
        }
    }
}

// --------------- bucket edges by dst ----------------------------------------
__global__ void bucket_kernel(int Et) {
    int e = blockIdx.x * blockDim.x + threadIdx.x;
    if (e >= Et) return;
    int2 sd = g_edges[e];
    int pos = atomicAdd(&g_cursor[sd.y], 1);
    g_csr_src[pos] = sd.x;
}

// --------------- GEMM1 (tf32 mma) + layer-1 logits fused ---------------------
#define AS_STRIDE 20
#define BS_STRIDE 132
#define ASZ (128 * AS_STRIDE)
#define BSZ (16 * BS_STRIDE)
#define HST_STRIDE 132   // halves per staged row; 132*2=264B, 8B-aligned rows

union GemmSmem {
    struct { float As[2][ASZ]; float Bs[2][BSZ]; } g;   // 37376 B
    __half hst[128][HST_STRIDE];                        // 33792 B
};

__device__ __forceinline__ unsigned sptr(const void* p) {
    return (unsigned)__cvta_generic_to_shared(p);
}
__device__ __forceinline__ void cpa16(unsigned dst, const void* src, int pbytes) {
    asm volatile("cp.async.ca.shared.global [%0], [%1], 16, %2;"
                 :: "r"(dst), "l"(src), "r"(pbytes));
}
__device__ __forceinline__ void cp_commit() {
    asm volatile("cp.async.commit_group;");
}
template <int NN> __device__ __forceinline__ void cp_wait() {
    asm volatile("cp.async.wait_group %0;" :: "n"(NN));
}
__device__ __forceinline__ void mma_tf32(float* c, const float* a, const float* b) {
    asm volatile(
        "mma.sync.aligned.m16n8k8.row.col.f32.tf32.tf32.f32 "
        "{%0,%1,%2,%3}, {%4,%5,%6,%7}, {%8,%9}, {%0,%1,%2,%3};"
        : "+f"(c[0]), "+f"(c[1]), "+f"(c[2]), "+f"(c[3])
        : "r"(__float_as_uint(a[0])), "r"(__float_as_uint(a[1])),
          "r"(__float_as_uint(a[2])), "r"(__float_as_uint(a[3])),
          "r"(__float_as_uint(b[0])), "r"(__float_as_uint(b[1])));
}

__global__ __launch_bounds__(256) void gemm1_kernel(const float* __restrict__ A,
                                                    const float* __restrict__ B,
                                                    const float* __restrict__ a_src,
                                                    const float* __restrict__ a_dst,
                                                    int M) {
    __shared__ GemmSmem su;
    __shared__ float sa1[F1], sd1[F1];
    int tid = threadIdx.x;
    if (tid < F1) { sa1[tid] = a_src[tid]; sd1[tid] = a_dst[tid]; }
    int warp = tid >> 5, lane = tid & 31;
    int warp_m = warp >> 1, warp_n = warp & 1;     // 4x2 warps: 32x64 per warp
    int row0 = blockIdx.x * 128;

    int lrow = tid >> 1;                 // A load: 0..127
    int lcb  = (tid & 1) * 8;            // col base 0 or 8
    int lk   = tid >> 4;                 // B load: 0..15
    int lnb  = (tid & 15) * 8;

    float acc[2][8][4];
#pragma unroll
    for (int i = 0; i < 2; i++)
#pragma unroll
        for (int j = 0; j < 8; j++)
#pragma unroll
            for (int q = 0; q < 4; q++) acc[i][j][q] = 0.f;

    int apb = (row0 + lrow < M) ? 16 : 0;

    {
        unsigned da = sptr(&su.g.As[0][lrow * AS_STRIDE + lcb]);
        cpa16(da,      A + (size_t)(row0 + lrow) * IN_C + lcb, apb);
        cpa16(da + 16, A + (size_t)(row0 + lrow) * IN_C + lcb + 4, apb);
        unsigned db = sptr(&su.g.Bs[0][lk * BS_STRIDE + lnb]);
        cpa16(db,      B + (size_t)lk * F1 + lnb, 16);
        cpa16(db + 16, B + (size_t)lk * F1 + lnb + 4, 16);
        cp_commit();
    }

    int r = lane >> 2, c = lane & 3;
#pragma unroll 1
    for (int t = 0; t < 16; t++) {
        int buf = t & 1;
        if (t < 15) {
            int k0 = (t + 1) * 16;
            unsigned da = sptr(&su.g.As[buf ^ 1][lrow * AS_STRIDE + lcb]);
            cpa16(da,      A + (size_t)(row0 + lrow) * IN_C + k0 + lcb, apb);
            cpa16(da + 16, A + (size_t)(row0 + lrow) * IN_C + k0 + lcb + 4, apb);
            unsigned db = sptr(&su.g.Bs[buf ^ 1][lk * BS_STRIDE + lnb]);
            cpa16(db,      B + (size_t)(k0 + lk) * F1 + lnb, 16);
            cpa16(db + 16, B + (size_t)(k0 + lk) * F1 + lnb + 4, 16);
            cp_commit();
            cp_wait<1>();
        } else {
            cp_wait<0>();
        }
        __syncthreads();

        const float* as = su.g.As[buf];
        const float* bs = su.g.Bs[buf];
#pragma unroll
        for (int ks = 0; ks < 2; ks++) {
            int k8 = ks * 8;
            float af[2][4];
#pragma unroll
            for (int mf = 0; mf < 2; mf++) {
                int rb = warp_m * 32 + mf * 16 + r;
                af[mf][0] = as[rb * AS_STRIDE + k8 + c];
                af[mf][1] = as[(rb + 8) * AS_STRIDE + k8 + c];
                af[mf][2] = as[rb * AS_STRIDE + k8 + c + 4];
                af[mf][3] = as[(rb + 8) * AS_STRIDE + k8 + c + 4];
            }
            float bf[8][2];
#pragma unroll
            for (int nf = 0; nf < 8; nf++) {
                int nn = warp_n * 64 + nf * 8 + r;
                bf[nf][0] = bs[(k8 + c) * BS_STRIDE + nn];
                bf[nf][1] = bs[(k8 + c + 4) * BS_STRIDE + nn];
            }
#pragma unroll
            for (int mf = 0; mf < 2; mf++)
#pragma unroll
                for (int nf = 0; nf < 8; nf++)
                    mma_tf32(acc[mf][nf], af[mf], bf[nf]);
        }
        __syncthreads();
    }

    // epilogue: fp16 convert; write global h1 AND stage into smem (As/Bs dead)
#pragma unroll
    for (int mf = 0; mf < 2; mf++) {
        int rl = warp_m * 32 + mf * 16 + r;        // local row
#pragma unroll
        for (int nf = 0; nf < 8; nf++) {
            int cb = warp_n * 64 + nf * 8 + c * 2;
            __half2 p0 = __float22half2_rn(make_float2(acc[mf][nf][0], acc[mf][nf][1]));
            __half2 p1 = __float22half2_rn(make_float2(acc[mf][nf][2], acc[mf][nf][3]));
            *(__half2*)(g_h1h + (size_t)(row0 + rl) * F1 + cb)     = p0;
            *(__half2*)(g_h1h + (size_t)(row0 + rl + 8) * F1 + cb) = p1;
            *(__half2*)&su.hst[rl][cb]     = p0;
            *(__half2*)&su.hst[rl + 8][cb] = p1;
        }
    }
    __syncthreads();

    // fused layer-1 logits: warp handles 16 local nodes from smem stage
#pragma unroll 1
    for (int i = 0; i < 16; i++) {
        int nl = warp * 16 + i;
        int node = row0 + nl;
        if (node >= M) break;
        uint2 raw = *(const uint2*)&su.hst[nl][lane * 4];
        float2 f01 = __half22float2(*(__half2*)&raw.x);
        float2 f23 = __half22float2(*(__half2*)&raw.y);
        float4 a  = *(const float4*)(sa1 + lane * 4);
        float4 b  = *(const float4*)(sd1 + lane * 4);
        float s = f01.x * a.x + f01.y * a.y + f23.x * a.z + f23.y * a.w;
        float d = f01.x * b.x + f01.y * b.y + f23.x * b.z + f23.y * b.w;
        s += __shfl_xor_sync(0xffffffffu, s, 1);
        s += __shfl_xor_sync(0xffffffffu, s, 2);
        d += __shfl_xor_sync(0xffffffffu, d, 1);
        d += __shfl_xor_sync(0xffffffffu, d, 2);
        if ((lane & 3) == 0) {
            g_als1[node * HEADS + (lane >> 2)] = s;
            g_ald1[node * HEADS + (lane >> 2)] = d;
        }
    }
}

// --------------- layer-1 aggregation + GEMM2 + layer-2 logits fused -----------
__global__ __launch_bounds__(256) void agg1_kernel(const float* __restrict__ b1,
                                                   const float* __restrict__ W2,
                                                   const float* __restrict__ as2,
                                                   const float* __restrict__ ad2, int n) {
    __shared__ float Ws[F1 * OUT_C];      // 16 KB
    __shared__ float rowbuf[8][F1];       // 4 KB
    __shared__ float sa[OUT_C], sb[OUT_C], sbias[F1];
    int tid = threadIdx.x;
#pragma unroll
    for (int i = 0; i < 4; i++) {
        int idx = tid * 4 + i * 1024;
        *(float4*)&Ws[idx] = *(const float4*)(W2 + idx);
    }
    if (tid < OUT_C) { sa[tid] = as2[tid]; sb[tid] = ad2[tid]; }
    if (tid < F1)    sbias[tid] = b1[tid];
    __syncthreads();

    int warp = tid >> 5, lane = tid & 31;
    int d = blockIdx.x * 8 + warp;
    if (d >= n) return;
    int h = lane >> 2;
    float ald = g_ald1[d * HEADS + h];
    int beg = g_rowptr[d];
    int cnt = g_rowptr[d + 1] - beg;
    const int* srcs = g_csr_src + beg;
    float ax = 0.f, ay = 0.f, az = 0.f, aw = 0.f, den = 0.f;
    int j = 0;
    for (; j + 4 <= cnt; j += 4) {
        int s0 = __ldg(srcs + j + 0);
        int s1 = __ldg(srcs + j + 1);
        int s2 = __ldg(srcs + j + 2);
        int s3 = __ldg(srcs + j + 3);
        float l0 = __ldg(g_als1 + s0 * HEADS + h);
        float l1 = __ldg(g_als1 + s1 * HEADS + h);
        float l2 = __ldg(g_als1 + s2 * HEADS + h);
        float l3 = __ldg(g_als1 + s3 * HEADS + h);
        uint2 r0 = *(const uint2*)(g_h1h + (size_t)s0 * F1 + lane * 4);
        uint2 r1 = *(const uint2*)(g_h1h + (size_t)s1 * F1 + lane * 4);
        uint2 r2 = *(const uint2*)(g_h1h + (size_t)s2 * F1 + lane * 4);
        uint2 r3 = *(const uint2*)(g_h1h + (size_t)s3 * F1 + lane * 4);
        float w0 = __expf(lrelu(l0 + ald));
        float w1 = __expf(lrelu(l1 + ald));
        float w2 = __expf(lrelu(l2 + ald));
        float w3 = __expf(lrelu(l3 + ald));
        float2 p0a = __half22float2(*(__half2*)&r0.x), p0b = __half22float2(*(__half2*)&r0.y);
        float2 p1a = __half22float2(*(__half2*)&r1.x), p1b = __half22float2(*(__half2*)&r1.y);
        float2 p2a = __half22float2(*(__half2*)&r2.x), p2b = __half22float2(*(__half2*)&r2.y);
        float2 p3a = __half22float2(*(__half2*)&r3.x), p3b = __half22float2(*(__half2*)&r3.y);
        ax += w0 * p0a.x + w1 * p1a.x + w2 * p2a.x + w3 * p3a.x;
        ay += w0 * p0a.y + w1 * p1a.y + w2 * p2a.y + w3 * p3a.y;
        az += w0 * p0b.x + w1 * p1b.x + w2 * p2b.x + w3 * p3b.x;
        aw += w0 * p0b.y + w1 * p1b.y + w2 * p2b.y + w3 * p3b.y;
        den += (w0 + w1) + (w2 + w3);
    }
    for (; j < cnt; j++) {
        int s = __ldg(srcs + j);
        float w = __expf(lrelu(__ldg(g_als1 + s * HEADS + h) + ald));
        uint2 r0 = *(const uint2*)(g_h1h + (size_t)s * F1 + lane * 4);
        float2 pa = __half22float2(*(__half2*)&r0.x), pb = __half22float2(*(__half2*)&r0.y);
        ax += w * pa.x; ay += w * pa.y; az += w * pb.x; aw += w * pb.y;
        den += w;
    }
    float inv = 1.f / (den + 1e-16f);
    float4 bb = *(const float4*)(sbias + lane * 4);
    float4 o;
    o.x = fmaxf(ax * inv + bb.x, 0.f);
    o.y = fmaxf(ay * inv + bb.y, 0.f);
    o.z = fmaxf(az * inv + bb.z, 0.f);
    o.w = fmaxf(aw * inv + bb.w, 0.f);

    *(float4*)&rowbuf[warp][lane * 4] = o;
    __syncwarp();
    float acc = 0.f;
#pragma unroll
    for (int k0 = 0; k0 < F1; k0 += 4) {
        float4 rv = *(const float4*)&rowbuf[warp][k0];
        acc += rv.x * Ws[(k0 + 0) * OUT_C + lane];
        acc += rv.y * Ws[(k0 + 1) * OUT_C + lane];
        acc += rv.z * Ws[(k0 + 2) * OUT_C + lane];
        acc += rv.w * Ws[(k0 + 3) * OUT_C + lane];
    }
    g_h2h[(size_t)d * OUT_C + lane] = __float2half_rn(acc);

    float s2v = acc * sa[lane];
    float d2v = acc * sb[lane];
#pragma unroll
    for (int o2 = 16; o2; o2 >>= 1) {
        s2v += __shfl_xor_sync(0xffffffffu, s2v, o2);
        d2v += __shfl_xor_sync(0xffffffffu, d2v, o2);
    }
    if (lane == 0) { g_als2[d] = s2v; g_ald2[d] = d2v; }
}

// --------------- layer-2 aggregation + bias + log_softmax fused ---------------
__global__ __launch_bounds__(256) void agg2_kernel(const float* __restrict__ b2,
                                                   float* __restrict__ out, int n) {
    int tid = threadIdx.x;
    int warp = tid >> 5, lane = tid & 31;
    int d = blockIdx.x * 8 + warp;
    if (d >= n) return;
    float ald = g_ald2[d];
    int beg = g_rowptr[d];
    int cnt = g_rowptr[d + 1] - beg;
    const int* srcs = g_csr_src + beg;
    float acc = 0.f, den = 0.f;
    int j = 0;
    for (; j + 4 <= cnt; j += 4) {
        int s0 = __ldg(srcs + j + 0);
        int s1 = __ldg(srcs + j + 1);
        int s2 = __ldg(srcs + j + 2);
        int s3 = __ldg(srcs + j + 3);
        float l0 = __ldg(g_als2 + s0);
        float l1 = __ldg(g_als2 + s1);
        float l2 = __ldg(g_als2 + s2);
        float l3 = __ldg(g_als2 + s3);
        float h0 = __half2float(g_h2h[(size_t)s0 * OUT_C + lane]);
        float h1v = __half2float(g_h2h[(size_t)s1 * OUT_C + lane]);
        float h2v = __half2float(g_h2h[(size_t)s2 * OUT_C + lane]);
        float h3 = __half2float(g_h2h[(size_t)s3 * OUT_C + lane]);
        float w0 = __expf(lrelu(l0 + ald));
        float w1 = __expf(lrelu(l1 + ald));
        float w2 = __expf(lrelu(l2 + ald));
        float w3 = __expf(lrelu(l3 + ald));
        acc += w0 * h0 + w1 * h1v + w2 * h2v + w3 * h3;
        den += (w0 + w1) + (w2 + w3);
    }
    for (; j < cnt; j++) {
        int s = __ldg(srcs + j);
        float w = __expf(lrelu(__ldg(g_als2 + s) + ald));
        acc += w * __half2float(g_h2h[(size_t)s * OUT_C + lane]);
        den += w;
    }
    float v = acc / (den + 1e-16f) + b2[lane];
    float mx = v;
#pragma unroll
    for (int o = 16; o; o >>= 1) mx = fmaxf(mx, __shfl_xor_sync(0xffffffffu, mx, o));
    float ex = __expf(v - mx);
    float sum = ex;
#pragma unroll
    for (int o = 16; o; o >>= 1) sum += __shfl_xor_sync(0xffffffffu, sum, o);
    out[(size_t)d * OUT_C + lane] = v - mx - logf(sum);
}

// --------------- launcher ------------------------------------------------------
extern "C" void kernel_launch(void* const* d_in, const int* in_sizes, int n_in,
                              void* d_out, int out_size) {
    const float* x   = (const float*)d_in[0];
    const void*  ei  = d_in[1];
    const float* W1  = (const float*)d_in[2];
    const float* as1 = (const float*)d_in[3];
    const float* ad1 = (const float*)d_in[4];
    const float* b1  = (const float*)d_in[5];
    const float* W2  = (const float*)d_in[6];
    const float* as2 = (const float*)d_in[7];
    const float* ad2 = (const float*)d_in[8];
    const float* b2  = (const float*)d_in[9];

    int n  = in_sizes[0] / IN_C;
    int E  = in_sizes[1] / 2;
    int Et = E + n;
    int nb1024 = (n + 1023) / 1024;
    int NB1 = (n + 7) / 8;

    prep_kernel<<<(Et + 255) / 256, 256>>>(ei, E, Et);
    gemm1_kernel<<<(n + 127) / 128, 256>>>(x, W1, as1, ad1, n);
    scan_kernel<<<nb1024, 1024>>>(n, nb1024, Et);
    bucket_kernel<<<(Et + 255) / 256, 256>>>(Et);
    agg1_kernel<<<NB1, 256>>>(b1, W2, as2, ad2, n);
    agg2_kernel<<<NB1, 256>>>(b2, (float*)d_out, n);
}

// round 11
// speedup vs baseline: 1.0729x; 1.0729x over previous
#include <cuda_runtime.h>
#include <cuda_fp16.h>
#include <cstdint>

#define IN_C    256
#define HID     16
#define HEADS   8
#define F1      128     // HEADS*HID
#define OUT_C   32
#define SLOPE   0.2f
#define N_MAX   50048
#define E_MAX   851968  // E + N headroom

// ---------------- scratch (device globals; no allocation allowed) ----------
__device__ int2     g_edges  [E_MAX];
__device__ int      g_csr_src[E_MAX];
__device__ int      g_cnt    [N_MAX];        // zero at entry; scan re-zeroes
__device__ int      g_rowptr [N_MAX + 1];
__device__ int      g_cursor [N_MAX];
__device__ int      g_bsum   [64];
__device__ int      g_ctr1;                  // zero at entry; scan resets
__device__ int      g_ctr2;
__device__ int      g_done;
__device__ __half   g_h1h [(size_t)N_MAX * F1];
__device__ float    g_als1[(size_t)N_MAX * HEADS];
__device__ float    g_ald1[(size_t)N_MAX * HEADS];
__device__ __half   g_h2h [(size_t)N_MAX * OUT_C];
__device__ float    g_als2[N_MAX];
__device__ float    g_ald2[N_MAX];

__device__ __forceinline__ float lrelu(float v) { return v > 0.f ? v : SLOPE * v; }

// --------------- edge decode + degree histogram (inline dtype detect) --------
__global__ void prep_kernel(const void* ei, int E, int Et) {
    __shared__ int s_is64;
    if (threadIdx.x == 0) {
        const int* p = (const int*)ei;
        int all0 = 1;
#pragma unroll
        for (int k = 1; k < 64; k += 2) all0 &= (p[k] == 0);
        s_is64 = all0;
    }
    __syncthreads();
    int e = blockIdx.x * blockDim.x + threadIdx.x;
    if (e >= Et) return;
    int s, d;
    if (e < E) {
        if (s_is64) {
            const long long* p = (const long long*)ei;
            s = (int)__ldg(p + e); d = (int)__ldg(p + (size_t)E + e);
        } else {
            const int* p = (const int*)ei;
            s = __ldg(p + e); d = __ldg(p + (size_t)E + e);
        }
    } else {
        s = d = e - E;
    }
    g_edges[e] = make_int2(s, d);
    atomicAdd(&g_cnt[d], 1);
}

// --------------- full scan in one kernel (co-resident spin release) ----------
// grid = ceil(n/1024) <= 49 blocks -> all co-resident on 148 SMs; spin is safe.
// (This exact pattern passed + timed in Rounds 7 and 8.)
__global__ __launch_bounds__(1024) void scan_kernel(int n, int nb, int Et) {
    __shared__ int sm[1024];
    __shared__ int amLast;
    int tid = threadIdx.x;
    int i = blockIdx.x * 1024 + tid;
    int v = (i < n) ? g_cnt[i] : 0;
    sm[tid] = v;
    __syncthreads();
    for (int off = 1; off < 1024; off <<= 1) {
        int t = (tid >= off) ? sm[tid - off] : 0;
        __syncthreads();
        sm[tid] += t;
        __syncthreads();
    }
    if (tid == 1023) g_bsum[blockIdx.x] = sm[1023];
    __threadfence();
    if (tid == 0) {
        int t = atomicAdd(&g_ctr1, 1);
        amLast = (t == (int)gridDim.x - 1);
    }
    __syncthreads();
    if (amLast && tid < 32) {
        int lane = tid;
        int a = (2 * lane < nb) ? g_bsum[2 * lane] : 0;
        int b = (2 * lane + 1 < nb) ? g_bsum[2 * lane + 1] : 0;
        int p = a + b;
#pragma unroll
        for (int off = 1; off < 32; off <<= 1) {
            int t = __shfl_up_sync(0xffffffffu, p, off);
            if (lane >= off) p += t;
        }
        int excl = p - (a + b);
        g_bsum[2 * lane]     = excl + a;
        g_bsum[2 * lane + 1] = excl + a + b;
        __threadfence();
        if (lane == 0) atomicExch(&g_done, 1);
    }
    if (tid == 0) {
        while (atomicAdd(&g_done, 0) == 0) { __nanosleep(64); }
    }
    __syncthreads();
    __threadfence();
    if (blockIdx.x == 0 && tid == 0) g_rowptr[n] = Et;
    if (i < n) {
        int pre = blockIdx.x ? __ldcg(&g_bsum[blockIdx.x - 1]) : 0;
        int start = sm[tid] - v + pre;
        g_rowptr[i] = start;
        g_cursor[i] = start;
        g_cnt[i] = 0;                            // restore precondition for replay
    }
    __threadfence();
    if (tid == 0) {
        int t2 = atomicAdd(&g_ctr2, 1);
        if (t2 == (int)gridDim.x - 1) {          // last to exit resets flags
            g_ctr1 = 0; g_ctr2 = 0; g_done = 0;
        }
    }
}

// --------------- GEMM1 (tf32 mma) + layer-1 logits + bucket, heterogeneous ---
#define AS_STRIDE 20
#define BS_STRIDE 132
#define ASZ (128 * AS_STRIDE)
#define BSZ (16 * BS_STRIDE)
#define HST_STRIDE 132

union GemmSmem {
    struct { float As[2][ASZ]; float Bs[2][BSZ]; } g;   // 37376 B
    __half hst[128][HST_STRIDE];                        // 33792 B
};

__device__ __forceinline__ unsigned sptr(const void* p) {
    return (unsigned)__cvta_generic_to_shared(p);
}
__device__ __forceinline__ void cpa16(unsigned dst, const void* src, int pbytes) {
    asm volatile("cp.async.ca.shared.global [%0], [%1], 16, %2;"
                 :: "r"(dst), "l"(src), "r"(pbytes));
}
__device__ __forceinline__ void cp_commit() {
    asm volatile("cp.async.commit_group;");
}
template <int NN> __device__ __forceinline__ void cp_wait() {
    asm volatile("cp.async.wait_group %0;" :: "n"(NN));
}
__device__ __forceinline__ void mma_tf32(float* c, const float* a, const float* b) {
    asm volatile(
        "mma.sync.aligned.m16n8k8.row.col.f32.tf32.tf32.f32 "
        "{%0,%1,%2,%3}, {%4,%5,%6,%7}, {%8,%9}, {%0,%1,%2,%3};"
        : "+f"(c[0]), "+f"(c[1]), "+f"(c[2]), "+f"(c[3])
        : "r"(__float_as_uint(a[0])), "r"(__float_as_uint(a[1])),
          "r"(__float_as_uint(a[2])), "r"(__float_as_uint(a[3])),
          "r"(__float_as_uint(b[0])), "r"(__float_as_uint(b[1])));
}

__global__ __launch_bounds__(256) void fused_kernel(const float* __restrict__ A,
                                                    const float* __restrict__ B,
                                                    const float* __restrict__ a_src,
                                                    const float* __restrict__ a_dst,
                                                    int M, int NG, int Et) {
    if ((int)blockIdx.x >= NG) {
        // ---------------- bucket part: grid-stride over edges ----------------
        int nthr = ((int)gridDim.x - NG) * 256;
        for (int e = (blockIdx.x - NG) * 256 + threadIdx.x; e < Et; e += nthr) {
            int2 sd = __ldg(&g_edges[e]);
            int pos = atomicAdd(&g_cursor[sd.y], 1);
            g_csr_src[pos] = sd.x;
        }
        return;
    }
    // ---------------- gemm part ----------------
    __shared__ GemmSmem su;
    __shared__ float sa1[F1], sd1[F1];
    int tid = threadIdx.x;
    if (tid < F1) { sa1[tid] = a_src[tid]; sd1[tid] = a_dst[tid]; }
    int warp = tid >> 5, lane = tid & 31;
    int warp_m = warp >> 1, warp_n = warp & 1;
    int row0 = blockIdx.x * 128;

    int lrow = tid >> 1;
    int lcb  = (tid & 1) * 8;
    int lk   = tid >> 4;
    int lnb  = (tid & 15) * 8;

    float acc[2][8][4];
#pragma unroll
    for (int i = 0; i < 2; i++)
#pragma unroll
        for (int j = 0; j < 8; j++)
#pragma unroll
            for (int q = 0; q < 4; q++) acc[i][j][q] = 0.f;

    int apb = (row0 + lrow < M) ? 16 : 0;

    {
        unsigned da = sptr(&su.g.As[0][lrow * AS_STRIDE + lcb]);
        cpa16(da,      A + (size_t)(row0 + lrow) * IN_C + lcb, apb);
        cpa16(da + 16, A + (size_t)(row0 + lrow) * IN_C + lcb + 4, apb);
        unsigned db = sptr(&su.g.Bs[0][lk * BS_STRIDE + lnb]);
        cpa16(db,      B + (size_t)lk * F1 + lnb, 16);
        cpa16(db + 16, B + (size_t)lk * F1 + lnb + 4, 16);
        cp_commit();
    }

    int r = lane >> 2, c = lane & 3;
#pragma unroll 1
    for (int t = 0; t < 16; t++) {
        int buf = t & 1;
        if (t < 15) {
            int k0 = (t + 1) * 16;
            unsigned da = sptr(&su.g.As[buf ^ 1][lrow * AS_STRIDE + lcb]);
            cpa16(da,      A + (size_t)(row0 + lrow) * IN_C + k0 + lcb, apb);
            cpa16(da + 16, A + (size_t)(row0 + lrow) * IN_C + k0 + lcb + 4, apb);
            unsigned db = sptr(&su.g.Bs[buf ^ 1][lk * BS_STRIDE + lnb]);
            cpa16(db,      B + (size_t)(k0 + lk) * F1 + lnb, 16);
            cpa16(db + 16, B + (size_t)(k0 + lk) * F1 + lnb + 4, 16);
            cp_commit();
            cp_wait<1>();
        } else {
            cp_wait<0>();
        }
        __syncthreads();

        const float* as = su.g.As[buf];
        const float* bs = su.g.Bs[buf];
#pragma unroll
        for (int ks = 0; ks < 2; ks++) {
            int k8 = ks * 8;
            float af[2][4];
#pragma unroll
            for (int mf = 0; mf < 2; mf++) {
                int rb = warp_m * 32 + mf * 16 + r;
                af[mf][0] = as[rb * AS_STRIDE + k8 + c];
                af[mf][1] = as[(rb + 8) * AS_STRIDE + k8 + c];
                af[mf][2] = as[rb * AS_STRIDE + k8 + c + 4];
                af[mf][3] = as[(rb + 8) * AS_STRIDE + k8 + c + 4];
            }
            float bf[8][2];
#pragma unroll
            for (int nf = 0; nf < 8; nf++) {
                int nn = warp_n * 64 + nf * 8 + r;
                bf[nf][0] = bs[(k8 + c) * BS_STRIDE + nn];
                bf[nf][1] = bs[(k8 + c + 4) * BS_STRIDE + nn];
            }
#pragma unroll
            for (int mf = 0; mf < 2; mf++)
#pragma unroll
                for (int nf = 0; nf < 8; nf++)
                    mma_tf32(acc[mf][nf], af[mf], bf[nf]);
        }
        __syncthreads();
    }

    // epilogue: fp16 convert; write global h1 AND stage into smem (As/Bs dead)
#pragma unroll
    for (int mf = 0; mf < 2; mf++) {
        int rl = warp_m * 32 + mf * 16 + r;
#pragma unroll
        for (int nf = 0; nf < 8; nf++) {
            int cb = warp_n * 64 + nf * 8 + c * 2;
            __half2 p0 = __float22half2_rn(make_float2(acc[mf][nf][0], acc[mf][nf][1]));
            __half2 p1 = __float22half2_rn(make_float2(acc[mf][nf][2], acc[mf][nf][3]));
            *(__half2*)(g_h1h + (size_t)(row0 + rl) * F1 + cb)     = p0;
            *(__half2*)(g_h1h + (size_t)(row0 + rl + 8) * F1 + cb) = p1;
            *(__half2*)&su.hst[rl][cb]     = p0;
            *(__half2*)&su.hst[rl + 8][cb] = p1;
        }
    }
    __syncthreads();

    // fused layer-1 logits: warp handles 16 local nodes from smem stage
#pragma unroll 1
    for (int i = 0; i < 16; i++) {
        int nl = warp * 16 + i;
        int node = row0 + nl;
        if (node >= M) break;
        uint2 raw = *(const uint2*)&su.hst[nl][lane * 4];
        float2 f01 = __half22float2(*(__half2*)&raw.x);
        float2 f23 = __half22float2(*(__half2*)&raw.y);
        float4 a  = *(const float4*)(sa1 + lane * 4);
        float4 b  = *(const float4*)(sd1 + lane * 4);
        float s = f01.x * a.x + f01.y * a.y + f23.x * a.z + f23.y * a.w;
        float d = f01.x * b.x + f01.y * b.y + f23.x * b.z + f23.y * b.w;
        s += __shfl_xor_sync(0xffffffffu, s, 1);
        s += __shfl_xor_sync(0xffffffffu, s, 2);
        d += __shfl_xor_sync(0xffffffffu, d, 1);
        d += __shfl_xor_sync(0xffffffffu, d, 2);
        if ((lane & 3) == 0) {
            g_als1[node * HEADS + (lane >> 2)] = s;
            g_ald1[node * HEADS + (lane >> 2)] = d;
        }
    }
}

// --------------- layer-1 aggregation + GEMM2 + layer-2 logits fused -----------
__global__ __launch_bounds__(256) void agg1_kernel(const float* __restrict__ b1,
                                                   const float* __restrict__ W2,
                                                   const float* __restrict__ as2,
                                                   const float* __restrict__ ad2, int n) {
    __shared__ float Ws[F1 * OUT_C];      // 16 KB
    __shared__ float rowbuf[8][F1];       // 4 KB
    __shared__ float sa[OUT_C], sb[OUT_C], sbias[F1];
    int tid = threadIdx.x;
#pragma unroll
    for (int i = 0; i < 4; i++) {
        int idx = tid * 4 + i * 1024;
        *(float4*)&Ws[idx] = *(const float4*)(W2 + idx);
    }
    if (tid < OUT_C) { sa[tid] = as2[tid]; sb[tid] = ad2[tid]; }
    if (tid < F1)    sbias[tid] = b1[tid];
    __syncthreads();

    int warp = tid >> 5, lane = tid & 31;
    int d = blockIdx.x * 8 + warp;
    if (d >= n) return;
    int h = lane >> 2;
    float ald = g_ald1[d * HEADS + h];
    int beg = g_rowptr[d];
    int cnt = g_rowptr[d + 1] - beg;
    const int* srcs = g_csr_src + beg;
    float ax = 0.f, ay = 0.f, az = 0.f, aw = 0.f, den = 0.f;
    int j = 0;
    for (; j + 8 <= cnt; j += 8) {
        int   si[8];
        float li[8];
        uint2 ri[8];
#pragma unroll
        for (int q = 0; q < 8; q++) si[q] = __ldg(srcs + j + q);
#pragma unroll
        for (int q = 0; q < 8; q++) li[q] = __ldg(g_als1 + si[q] * HEADS + h);
#pragma unroll
        for (int q = 0; q < 8; q++) ri[q] = *(const uint2*)(g_h1h + (size_t)si[q] * F1 + lane * 4);
#pragma unroll
        for (int q = 0; q < 8; q++) {
            float w = __expf(lrelu(li[q] + ald));
            float2 pa = __half22float2(*(__half2*)&ri[q].x);
            float2 pb = __half22float2(*(__half2*)&ri[q].y);
            ax += w * pa.x; ay += w * pa.y; az += w * pb.x; aw += w * pb.y;
            den += w;
        }
    }
    for (; j + 4 <= cnt; j += 4) {
        int s0 = __ldg(srcs + j + 0);
        int s1 = __ldg(srcs + j + 1);
        int s2 = __ldg(srcs + j + 2);
        int s3 = __ldg(srcs + j + 3);
        float l0 = __ldg(g_als1 + s0 * HEADS + h);
        float l1 = __ldg(g_als1 + s1 * HEADS + h);
        float l2 = __ldg(g_als1 + s2 * HEADS + h);
        float l3 = __ldg(g_als1 + s3 * HEADS + h);
        uint2 r0 = *(const uint2*)(g_h1h + (size_t)s0 * F1 + lane * 4);
        uint2 r1 = *(const uint2*)(g_h1h + (size_t)s1 * F1 + lane * 4);
        uint2 r2 = *(const uint2*)(g_h1h + (size_t)s2 * F1 + lane * 4);
        uint2 r3 = *(const uint2*)(g_h1h + (size_t)s3 * F1 + lane * 4);
        float w0 = __expf(lrelu(l0 + ald));
        float w1 = __expf(lrelu(l1 + ald));
        float w2 = __expf(lrelu(l2 + ald));
        float w3 = __expf(lrelu(l3 + ald));
        float2 p0a = __half22float2(*(__half2*)&r0.x), p0b = __half22float2(*(__half2*)&r0.y);
        float2 p1a = __half22float2(*(__half2*)&r1.x), p1b = __half22float2(*(__half2*)&r1.y);
        float2 p2a = __half22float2(*(__half2*)&r2.x), p2b = __half22float2(*(__half2*)&r2.y);
        float2 p3a = __half22float2(*(__half2*)&r3.x), p3b = __half22float2(*(__half2*)&r3.y);
        ax += w0 * p0a.x + w1 * p1a.x + w2 * p2a.x + w3 * p3a.x;
        ay += w0 * p0a.y + w1 * p1a.y + w2 * p2a.y + w3 * p3a.y;
        az += w0 * p0b.x + w1 * p1b.x + w2 * p2b.x + w3 * p3b.x;
        aw += w0 * p0b.y + w1 * p1b.y + w2 * p2b.y + w3 * p3b.y;
        den += (w0 + w1) + (w2 + w3);
    }
    for (; j < cnt; j++) {
        int s = __ldg(srcs + j);
        float w = __expf(lrelu(__ldg(g_als1 + s * HEADS + h) + ald));
        uint2 r0 = *(const uint2*)(g_h1h + (size_t)s * F1 + lane * 4);
        float2 pa = __half22float2(*(__half2*)&r0.x), pb = __half22float2(*(__half2*)&r0.y);
        ax += w * pa.x; ay += w * pa.y; az += w * pb.x; aw += w * pb.y;
        den += w;
    }
    float inv = 1.f / (den + 1e-16f);
    float4 bb = *(const float4*)(sbias + lane * 4);
    float4 o;
    o.x = fmaxf(ax * inv + bb.x, 0.f);
    o.y = fmaxf(ay * inv + bb.y, 0.f);
    o.z = fmaxf(az * inv + bb.z, 0.f);
    o.w = fmaxf(aw * inv + bb.w, 0.f);

    *(float4*)&rowbuf[warp][lane * 4] = o;
    __syncwarp();
    float acc = 0.f;
#pragma unroll
    for (int k0 = 0; k0 < F1; k0 += 4) {
        float4 rv = *(const float4*)&rowbuf[warp][k0];
        acc += rv.x * Ws[(k0 + 0) * OUT_C + lane];
        acc += rv.y * Ws[(k0 + 1) * OUT_C + lane];
        acc += rv.z * Ws[(k0 + 2) * OUT_C + lane];
        acc += rv.w * Ws[(k0 + 3) * OUT_C + lane];
    }
    g_h2h[(size_t)d * OUT_C + lane] = __float2half_rn(acc);

    float s2v = acc * sa[lane];
    float d2v = acc * sb[lane];
#pragma unroll
    for (int o2 = 16; o2; o2 >>= 1) {
        s2v += __shfl_xor_sync(0xffffffffu, s2v, o2);
        d2v += __shfl_xor_sync(0xffffffffu, d2v, o2);
    }
    if (lane == 0) { g_als2[d] = s2v; g_ald2[d] = d2v; }
}

// --------------- layer-2 aggregation + bias + log_softmax fused ---------------
__global__ __launch_bounds__(256) void agg2_kernel(const float* __restrict__ b2,
                                                   float* __restrict__ out, int n) {
    int tid = threadIdx.x;
    int warp = tid >> 5, lane = tid & 31;
    int d = blockIdx.x * 8 + warp;
    if (d >= n) return;
    float ald = g_ald2[d];
    int beg = g_rowptr[d];
    int cnt = g_rowptr[d + 1] - beg;
    const int* srcs = g_csr_src + beg;
    float acc = 0.f, den = 0.f;
    int j = 0;
    for (; j + 4 <= cnt; j += 4) {
        int s0 = __ldg(srcs + j + 0);
        int s1 = __ldg(srcs + j + 1);
        int s2 = __ldg(srcs + j + 2);
        int s3 = __ldg(srcs + j + 3);
        float l0 = __ldg(g_als2 + s0);
        float l1 = __ldg(g_als2 + s1);
        float l2 = __ldg(g_als2 + s2);
        float l3 = __ldg(g_als2 + s3);
        float h0 = __half2float(g_h2h[(size_t)s0 * OUT_C + lane]);
        float h1v = __half2float(g_h2h[(size_t)s1 * OUT_C + lane]);
        float h2v = __half2float(g_h2h[(size_t)s2 * OUT_C + lane]);
        float h3 = __half2float(g_h2h[(size_t)s3 * OUT_C + lane]);
        float w0 = __expf(lrelu(l0 + ald));
        float w1 = __expf(lrelu(l1 + ald));
        float w2 = __expf(lrelu(l2 + ald));
        float w3 = __expf(lrelu(l3 + ald));
        acc += w0 * h0 + w1 * h1v + w2 * h2v + w3 * h3;
        den += (w0 + w1) + (w2 + w3);
    }
    for (; j < cnt; j++) {
        int s = __ldg(srcs + j);
        float w = __expf(lrelu(__ldg(g_als2 + s) + ald));
        acc += w * __half2float(g_h2h[(size_t)s * OUT_C + lane]);
        den += w;
    }
    float v = acc / (den + 1e-16f) + b2[lane];
    float mx = v;
#pragma unroll
    for (int o = 16; o; o >>= 1) mx = fmaxf(mx, __shfl_xor_sync(0xffffffffu, mx, o));
    float ex = __expf(v - mx);
    float sum = ex;
#pragma unroll
    for (int o = 16; o; o >>= 1) sum += __shfl_xor_sync(0xffffffffu, sum, o);
    out[(size_t)d * OUT_C + lane] = v - mx - logf(sum);
}

// --------------- launcher ------------------------------------------------------
extern "C" void kernel_launch(void* const* d_in, const int* in_sizes, int n_in,
                              void* d_out, int out_size) {
    const float* x   = (const float*)d_in[0];
    const void*  ei  = d_in[1];
    const float* W1  = (const float*)d_in[2];
    const float* as1 = (const float*)d_in[3];
    const float* ad1 = (const float*)d_in[4];
    const float* b1  = (const float*)d_in[5];
    const float* W2  = (const float*)d_in[6];
    const float* as2 = (const float*)d_in[7];
    const float* ad2 = (const float*)d_in[8];
    const float* b2  = (const float*)d_in[9];

    int n  = in_sizes[0] / IN_C;
    int E  = in_sizes[1] / 2;
    int Et = E + n;
    int nb1024 = (n + 1023) / 1024;
    int NB1 = (n + 7) / 8;
    int NG  = (n + 127) / 128;       // gemm blocks
    int NBK = 1184;                  // bucket blocks (8/SM worth; backfill gemm wave 2)

    prep_kernel<<<(Et + 255) / 256, 256>>>(ei, E, Et);
    scan_kernel<<<nb1024, 1024>>>(n, nb1024, Et);
    fused_kernel<<<NG + NBK, 256>>>(x, W1, as1, ad1, n, NG, Et);
    agg1_kernel<<<NB1, 256>>>(b1, W2, as2, ad2, n);
    agg2_kernel<<<NB1, 256>>>(b2, (float*)d_out, n);
}

// round 12
// speedup vs baseline: 1.0733x; 1.0004x over previous
#include <cuda_runtime.h>
#include <cuda_fp16.h>
#include <cstdint>

#define IN_C    256
#define HID     16
#define HEADS   8
#define F1      128     // HEADS*HID
#define OUT_C   32
#define SLOPE   0.2f
#define N_MAX   50048
#define E_MAX   851968  // E + N headroom

// ---------------- scratch (device globals; no allocation allowed) ----------
__device__ int2     g_edges  [E_MAX];
__device__ int      g_csr_src[E_MAX];
__device__ int      g_cnt    [N_MAX];        // zero at entry; scan re-zeroes
__device__ int      g_rowptr [N_MAX + 1];
__device__ int      g_cursor [N_MAX];
__device__ int      g_bsum   [64];
__device__ int      g_ctr1;                  // zero at entry; scan resets
__device__ int      g_ctr2;
__device__ int      g_done;
__device__ __half   g_h1h [(size_t)N_MAX * F1];
__device__ float    g_als1[(size_t)N_MAX * HEADS];
__device__ float    g_ald1[(size_t)N_MAX * HEADS];
__device__ __half   g_h2h [(size_t)N_MAX * OUT_C];
__device__ float    g_als2[N_MAX];
__device__ float    g_ald2[N_MAX];

__device__ __forceinline__ float lrelu(float v) { return v > 0.f ? v : SLOPE * v; }

// L2-only (L1-bypass) loads for zero-reuse gathers
__device__ __forceinline__ uint2 ldcg_u2(const void* p) {
    uint2 r;
    asm volatile("ld.global.cg.v2.u32 {%0,%1}, [%2];"
                 : "=r"(r.x), "=r"(r.y) : "l"(p));
    return r;
}
__device__ __forceinline__ float ldcg_h(const __half* p) {
    unsigned short u;
    asm volatile("ld.global.cg.u16 %0, [%1];" : "=h"(u) : "l"(p));
    __half h = *(__half*)&u;
    return __half2float(h);
}

// --------------- edge decode + degree histogram (inline dtype detect) --------
__global__ void prep_kernel(const void* ei, int E, int Et) {
    __shared__ int s_is64;
    if (threadIdx.x == 0) {
        const int* p = (const int*)ei;
        int all0 = 1;
#pragma unroll
        for (int k = 1; k < 64; k += 2) all0 &= (p[k] == 0);
        s_is64 = all0;
    }
    __syncthreads();
    int e = blockIdx.x * blockDim.x + threadIdx.x;
    if (e >= Et) return;
    int s, d;
    if (e < E) {
        if (s_is64) {
            const long long* p = (const long long*)ei;
            s = (int)__ldg(p + e); d = (int)__ldg(p + (size_t)E + e);
        } else {
            const int* p = (const int*)ei;
            s = __ldg(p + e); d = __ldg(p + (size_t)E + e);
        }
    } else {
        s = d = e - E;
    }
    g_edges[e] = make_int2(s, d);
    atomicAdd(&g_cnt[d], 1);
}

// --------------- full scan in one kernel (co-resident spin release) ----------
// grid = ceil(n/1024) <= 49 blocks -> all co-resident on 148 SMs; spin is safe.
__global__ __launch_bounds__(1024) void scan_kernel(int n, int nb, int Et) {
    __shared__ int sm[1024];
    __shared__ int amLast;
    int tid = threadIdx.x;
    int i = blockIdx.x * 1024 + tid;
    int v = (i < n) ? g_cnt[i] : 0;
    sm[tid] = v;
    __syncthreads();
    for (int off = 1; off < 1024; off <<= 1) {
        int t = (tid >= off) ? sm[tid - off] : 0;
        __syncthreads();
        sm[tid] += t;
        __syncthreads();
    }
    if (tid == 1023) g_bsum[blockIdx.x] = sm[1023];
    __threadfence();
    if (tid == 0) {
        int t = atomicAdd(&g_ctr1, 1);
        amLast = (t == (int)gridDim.x - 1);
    }
    __syncthreads();
    if (amLast && tid < 32) {
        int lane = tid;
        int a = (2 * lane < nb) ? g_bsum[2 * lane] : 0;
        int b = (2 * lane + 1 < nb) ? g_bsum[2 * lane + 1] : 0;
        int p = a + b;
#pragma unroll
        for (int off = 1; off < 32; off <<= 1) {
            int t = __shfl_up_sync(0xffffffffu, p, off);
            if (lane >= off) p += t;
        }
        int excl = p - (a + b);
        g_bsum[2 * lane]     = excl + a;
        g_bsum[2 * lane + 1] = excl + a + b;
        __threadfence();
        if (lane == 0) atomicExch(&g_done, 1);
    }
    if (tid == 0) {
        while (atomicAdd(&g_done, 0) == 0) { __nanosleep(64); }
    }
    __syncthreads();
    __threadfence();
    if (blockIdx.x == 0 && tid == 0) g_rowptr[n] = Et;
    if (i < n) {
        int pre = blockIdx.x ? __ldcg(&g_bsum[blockIdx.x - 1]) : 0;
        int start = sm[tid] - v + pre;
        g_rowptr[i] = start;
        g_cursor[i] = start;
        g_cnt[i] = 0;                            // restore precondition for replay
    }
    __threadfence();
    if (tid == 0) {
        int t2 = atomicAdd(&g_ctr2, 1);
        if (t2 == (int)gridDim.x - 1) {          // last to exit resets flags
            g_ctr1 = 0; g_ctr2 = 0; g_done = 0;
        }
    }
}

// --------------- GEMM1 (tf32 mma) + layer-1 logits + bucket, heterogeneous ---
#define AS_STRIDE 20
#define BS_STRIDE 132
#define ASZ (128 * AS_STRIDE)
#define BSZ (16 * BS_STRIDE)
#define HST_STRIDE 132

union GemmSmem {
    struct { float As[2][ASZ]; float Bs[2][BSZ]; } g;   // 37376 B
    __half hst[128][HST_STRIDE];                        // 33792 B
};

__device__ __forceinline__ unsigned sptr(const void* p) {
    return (unsigned)__cvta_generic_to_shared(p);
}
__device__ __forceinline__ void cpa16(unsigned dst, const void* src, int pbytes) {
    asm volatile("cp.async.ca.shared.global [%0], [%1], 16, %2;"
                 :: "r"(dst), "l"(src), "r"(pbytes));
}
__device__ __forceinline__ void cp_commit() {
    asm volatile("cp.async.commit_group;");
}
template <int NN> __device__ __forceinline__ void cp_wait() {
    asm volatile("cp.async.wait_group %0;" :: "n"(NN));
}
__device__ __forceinline__ void mma_tf32(float* c, const float* a, const float* b) {
    asm volatile(
        "mma.sync.aligned.m16n8k8.row.col.f32.tf32.tf32.f32 "
        "{%0,%1,%2,%3}, {%4,%5,%6,%7}, {%8,%9}, {%0,%1,%2,%3};"
        : "+f"(c[0]), "+f"(c[1]), "+f"(c[2]), "+f"(c[3])
        : "r"(__float_as_uint(a[0])), "r"(__float_as_uint(a[1])),
          "r"(__float_as_uint(a[2])), "r"(__float_as_uint(a[3])),
          "r"(__float_as_uint(b[0])), "r"(__float_as_uint(b[1])));
}

__global__ __launch_bounds__(256) void fused_kernel(const float* __restrict__ A,
                                                    const float* __restrict__ B,
                                                    const float* __restrict__ a_src,
                                                    const float* __restrict__ a_dst,
                                                    int M, int NG, int Et) {
    if ((int)blockIdx.x >= NG) {
        // ---------------- bucket part: grid-stride over edges ----------------
        int nthr = ((int)gridDim.x - NG) * 256;
        for (int e = (blockIdx.x - NG) * 256 + threadIdx.x; e < Et; e += nthr) {
            int2 sd = __ldg(&g_edges[e]);
            int pos = atomicAdd(&g_cursor[sd.y], 1);
            g_csr_src[pos] = sd.x;
        }
        return;
    }
    // ---------------- gemm part ----------------
    __shared__ GemmSmem su;
    __shared__ float sa1[F1], sd1[F1];
    int tid = threadIdx.x;
    if (tid < F1) { sa1[tid] = a_src[tid]; sd1[tid] = a_dst[tid]; }
    int warp = tid >> 5, lane = tid & 31;
    int warp_m = warp >> 1, warp_n = warp & 1;
    int row0 = blockIdx.x * 128;

    int lrow = tid >> 1;
    int lcb  = (tid & 1) * 8;
    int lk   = tid >> 4;
    int lnb  = (tid & 15) * 8;

    float acc[2][8][4];
#pragma unroll
    for (int i = 0; i < 2; i++)
#pragma unroll
        for (int j = 0; j < 8; j++)
#pragma unroll
            for (int q = 0; q < 4; q++) acc[i][j][q] = 0.f;

    int apb = (row0 + lrow < M) ? 16 : 0;

    {
        unsigned da = sptr(&su.g.As[0][lrow * AS_STRIDE + lcb]);
        cpa16(da,      A + (size_t)(row0 + lrow) * IN_C + lcb, apb);
        cpa16(da + 16, A + (size_t)(row0 + lrow) * IN_C + lcb + 4, apb);
        unsigned db = sptr(&su.g.Bs[0][lk * BS_STRIDE + lnb]);
        cpa16(db,      B + (size_t)lk * F1 + lnb, 16);
        cpa16(db + 16, B + (size_t)lk * F1 + lnb + 4, 16);
        cp_commit();
    }

    int r = lane >> 2, c = lane & 3;
#pragma unroll 1
    for (int t = 0; t < 16; t++) {
        int buf = t & 1;
        if (t < 15) {
            int k0 = (t + 1) * 16;
            unsigned da = sptr(&su.g.As[buf ^ 1][lrow * AS_STRIDE + lcb]);
            cpa16(da,      A + (size_t)(row0 + lrow) * IN_C + k0 + lcb, apb);
            cpa16(da + 16, A + (size_t)(row0 + lrow) * IN_C + k0 + lcb + 4, apb);
            unsigned db = sptr(&su.g.Bs[buf ^ 1][lk * BS_STRIDE + lnb]);
            cpa16(db,      B + (size_t)(k0 + lk) * F1 + lnb, 16);
            cpa16(db + 16, B + (size_t)(k0 + lk) * F1 + lnb + 4, 16);
            cp_commit();
            cp_wait<1>();
        } else {
            cp_wait<0>();
        }
        __syncthreads();

        const float* as = su.g.As[buf];
        const float* bs = su.g.Bs[buf];
#pragma unroll
        for (int ks = 0; ks < 2; ks++) {
            int k8 = ks * 8;
            float af[2][4];
#pragma unroll
            for (int mf = 0; mf < 2; mf++) {
                int rb = warp_m * 32 + mf * 16 + r;
                af[mf][0] = as[rb * AS_STRIDE + k8 + c];
                af[mf][1] = as[(rb + 8) * AS_STRIDE + k8 + c];
                af[mf][2] = as[rb * AS_STRIDE + k8 + c + 4];
                af[mf][3] = as[(rb + 8) * AS_STRIDE + k8 + c + 4];
            }
            float bf[8][2];
#pragma unroll
            for (int nf = 0; nf < 8; nf++) {
                int nn = warp_n * 64 + nf * 8 + r;
                bf[nf][0] = bs[(k8 + c) * BS_STRIDE + nn];
                bf[nf][1] = bs[(k8 + c + 4) * BS_STRIDE + nn];
            }
#pragma unroll
            for (int mf = 0; mf < 2; mf++)
#pragma unroll
                for (int nf = 0; nf < 8; nf++)
                    mma_tf32(acc[mf][nf], af[mf], bf[nf]);
        }
        __syncthreads();
    }

    // epilogue: fp16 convert; write global h1 AND stage into smem (As/Bs dead)
#pragma unroll
    for (int mf = 0; mf < 2; mf++) {
        int rl = warp_m * 32 + mf * 16 + r;
#pragma unroll
        for (int nf = 0; nf < 8; nf++) {
            int cb = warp_n * 64 + nf * 8 + c * 2;
            __half2 p0 = __float22half2_rn(make_float2(acc[mf][nf][0], acc[mf][nf][1]));
            __half2 p1 = __float22half2_rn(make_float2(acc[mf][nf][2], acc[mf][nf][3]));
            *(__half2*)(g_h1h + (size_t)(row0 + rl) * F1 + cb)     = p0;
            *(__half2*)(g_h1h + (size_t)(row0 + rl + 8) * F1 + cb) = p1;
            *(__half2*)&su.hst[rl][cb]     = p0;
            *(__half2*)&su.hst[rl + 8][cb] = p1;
        }
    }
    __syncthreads();

    // fused layer-1 logits: warp handles 16 local nodes from smem stage
#pragma unroll 1
    for (int i = 0; i < 16; i++) {
        int nl = warp * 16 + i;
        int node = row0 + nl;
        if (node >= M) break;
        uint2 raw = *(const uint2*)&su.hst[nl][lane * 4];
        float2 f01 = __half22float2(*(__half2*)&raw.x);
        float2 f23 = __half22float2(*(__half2*)&raw.y);
        float4 a  = *(const float4*)(sa1 + lane * 4);
        float4 b  = *(const float4*)(sd1 + lane * 4);
        float s = f01.x * a.x + f01.y * a.y + f23.x * a.z + f23.y * a.w;
        float d = f01.x * b.x + f01.y * b.y + f23.x * b.z + f23.y * b.w;
        s += __shfl_xor_sync(0xffffffffu, s, 1);
        s += __shfl_xor_sync(0xffffffffu, s, 2);
        d += __shfl_xor_sync(0xffffffffu, d, 1);
        d += __shfl_xor_sync(0xffffffffu, d, 2);
        if ((lane & 3) == 0) {
            g_als1[node * HEADS + (lane >> 2)] = s;
            g_ald1[node * HEADS + (lane >> 2)] = d;
        }
    }
}

// --------------- layer-1 aggregation + GEMM2 + layer-2 logits fused -----------
__global__ __launch_bounds__(256) void agg1_kernel(const float* __restrict__ b1,
                                                   const float* __restrict__ W2,
                                                   const float* __restrict__ as2,
                                                   const float* __restrict__ ad2, int n) {
    __shared__ float Ws[F1 * OUT_C];      // 16 KB
    __shared__ float rowbuf[8][F1];       // 4 KB
    __shared__ float sa[OUT_C], sb[OUT_C], sbias[F1];
    int tid = threadIdx.x;
#pragma unroll
    for (int i = 0; i < 4; i++) {
        int idx = tid * 4 + i * 1024;
        *(float4*)&Ws[idx] = *(const float4*)(W2 + idx);
    }
    if (tid < OUT_C) { sa[tid] = as2[tid]; sb[tid] = ad2[tid]; }
    if (tid < F1)    sbias[tid] = b1[tid];
    __syncthreads();

    int warp = tid >> 5, lane = tid & 31;
    int d = blockIdx.x * 8 + warp;
    if (d >= n) return;
    int h = lane >> 2;
    float ald = g_ald1[d * HEADS + h];
    int beg = g_rowptr[d];
    int cnt = g_rowptr[d + 1] - beg;
    const int* srcs = g_csr_src + beg;
    const __half* h1base = g_h1h + lane * 4;
    float ax = 0.f, ay = 0.f, az = 0.f, aw = 0.f, den = 0.f;
    int j = 0;
    for (; j + 8 <= cnt; j += 8) {
        int   si[8];
        float li[8];
        uint2 ri[8];
#pragma unroll
        for (int q = 0; q < 8; q++) si[q] = __ldg(srcs + j + q);
#pragma unroll
        for (int q = 0; q < 8; q++) li[q] = __ldg(g_als1 + si[q] * HEADS + h);
#pragma unroll
        for (int q = 0; q < 8; q++) ri[q] = ldcg_u2(h1base + (size_t)si[q] * F1);
#pragma unroll
        for (int q = 0; q < 8; q++) {
            float w = __expf(lrelu(li[q] + ald));
            float2 pa = __half22float2(*(__half2*)&ri[q].x);
            float2 pb = __half22float2(*(__half2*)&ri[q].y);
            ax += w * pa.x; ay += w * pa.y; az += w * pb.x; aw += w * pb.y;
            den += w;
        }
    }
    for (; j + 4 <= cnt; j += 4) {
        int s0 = __ldg(srcs + j + 0);
        int s1 = __ldg(srcs + j + 1);
        int s2 = __ldg(srcs + j + 2);
        int s3 = __ldg(srcs + j + 3);
        float l0 = __ldg(g_als1 + s0 * HEADS + h);
        float l1 = __ldg(g_als1 + s1 * HEADS + h);
        float l2 = __ldg(g_als1 + s2 * HEADS + h);
        float l3 = __ldg(g_als1 + s3 * HEADS + h);
        uint2 r0 = ldcg_u2(h1base + (size_t)s0 * F1);
        uint2 r1 = ldcg_u2(h1base + (size_t)s1 * F1);
        uint2 r2 = ldcg_u2(h1base + (size_t)s2 * F1);
        uint2 r3 = ldcg_u2(h1base + (size_t)s3 * F1);
        float w0 = __expf(lrelu(l0 + ald));
        float w1 = __expf(lrelu(l1 + ald));
        float w2 = __expf(lrelu(l2 + ald));
        float w3 = __expf(lrelu(l3 + ald));
        float2 p0a = __half22float2(*(__half2*)&r0.x), p0b = __half22float2(*(__half2*)&r0.y);
        float2 p1a = __half22float2(*(__half2*)&r1.x), p1b = __half22float2(*(__half2*)&r1.y);
        float2 p2a = __half22float2(*(__half2*)&r2.x), p2b = __half22float2(*(__half2*)&r2.y);
        float2 p3a = __half22float2(*(__half2*)&r3.x), p3b = __half22float2(*(__half2*)&r3.y);
        ax += w0 * p0a.x + w1 * p1a.x + w2 * p2a.x + w3 * p3a.x;
        ay += w0 * p0a.y + w1 * p1a.y + w2 * p2a.y + w3 * p3a.y;
        az += w0 * p0b.x + w1 * p1b.x + w2 * p2b.x + w3 * p3b.x;
        aw += w0 * p0b.y + w1 * p1b.y + w2 * p2b.y + w3 * p3b.y;
        den += (w0 + w1) + (w2 + w3);
    }
    for (; j < cnt; j++) {
        int s = __ldg(srcs + j);
        float w = __expf(lrelu(__ldg(g_als1 + s * HEADS + h) + ald));
        uint2 r0 = ldcg_u2(h1base + (size_t)s * F1);
        float2 pa = __half22float2(*(__half2*)&r0.x), pb = __half22float2(*(__half2*)&r0.y);
        ax += w * pa.x; ay += w * pa.y; az += w * pb.x; aw += w * pb.y;
        den += w;
    }
    float inv = 1.f / (den + 1e-16f);
    float4 bb = *(const float4*)(sbias + lane * 4);
    float4 o;
    o.x = fmaxf(ax * inv + bb.x, 0.f);
    o.y = fmaxf(ay * inv + bb.y, 0.f);
    o.z = fmaxf(az * inv + bb.z, 0.f);
    o.w = fmaxf(aw * inv + bb.w, 0.f);

    *(float4*)&rowbuf[warp][lane * 4] = o;
    __syncwarp();
    float acc = 0.f;
#pragma unroll
    for (int k0 = 0; k0 < F1; k0 += 4) {
        float4 rv = *(const float4*)&rowbuf[warp][k0];
        acc += rv.x * Ws[(k0 + 0) * OUT_C + lane];
        acc += rv.y * Ws[(k0 + 1) * OUT_C + lane];
        acc += rv.z * Ws[(k0 + 2) * OUT_C + lane];
        acc += rv.w * Ws[(k0 + 3) * OUT_C + lane];
    }
    g_h2h[(size_t)d * OUT_C + lane] = __float2half_rn(acc);

    float s2v = acc * sa[lane];
    float d2v = acc * sb[lane];
#pragma unroll
    for (int o2 = 16; o2; o2 >>= 1) {
        s2v += __shfl_xor_sync(0xffffffffu, s2v, o2);
        d2v += __shfl_xor_sync(0xffffffffu, d2v, o2);
    }
    if (lane == 0) { g_als2[d] = s2v; g_ald2[d] = d2v; }
}

// --------------- layer-2 aggregation + bias + log_softmax fused ---------------
__global__ __launch_bounds__(256) void agg2_kernel(const float* __restrict__ b2,
                                                   float* __restrict__ out, int n) {
    int tid = threadIdx.x;
    int warp = tid >> 5, lane = tid & 31;
    int d = blockIdx.x * 8 + warp;
    if (d >= n) return;
    float ald = g_ald2[d];
    int beg = g_rowptr[d];
    int cnt = g_rowptr[d + 1] - beg;
    const int* srcs = g_csr_src + beg;
    const __half* h2base = g_h2h + lane;
    float acc = 0.f, den = 0.f;
    int j = 0;
    for (; j + 4 <= cnt; j += 4) {
        int s0 = __ldg(srcs + j + 0);
        int s1 = __ldg(srcs + j + 1);
        int s2 = __ldg(srcs + j + 2);
        int s3 = __ldg(srcs + j + 3);
        float l0 = __ldg(g_als2 + s0);
        float l1 = __ldg(g_als2 + s1);
        float l2 = __ldg(g_als2 + s2);
        float l3 = __ldg(g_als2 + s3);
        float h0 = ldcg_h(h2base + (size_t)s0 * OUT_C);
        float h1v = ldcg_h(h2base + (size_t)s1 * OUT_C);
        float h2v = ldcg_h(h2base + (size_t)s2 * OUT_C);
        float h3 = ldcg_h(h2base + (size_t)s3 * OUT_C);
        float w0 = __expf(lrelu(l0 + ald));
        float w1 = __expf(lrelu(l1 + ald));
        float w2 = __expf(lrelu(l2 + ald));
        float w3 = __expf(lrelu(l3 + ald));
        acc += w0 * h0 + w1 * h1v + w2 * h2v + w3 * h3;
        den += (w0 + w1) + (w2 + w3);
    }
    for (; j < cnt; j++) {
        int s = __ldg(srcs + j);
        float w = __expf(lrelu(__ldg(g_als2 + s) + ald));
        acc += w * ldcg_h(h2base + (size_t)s * OUT_C);
        den += w;
    }
    float v = acc / (den + 1e-16f) + b2[lane];
    float mx = v;
#pragma unroll
    for (int o = 16; o; o >>= 1) mx = fmaxf(mx, __shfl_xor_sync(0xffffffffu, mx, o));
    float ex = __expf(v - mx);
    float sum = ex;
#pragma unroll
    for (int o = 16; o; o >>= 1) sum += __shfl_xor_sync(0xffffffffu, sum, o);
    out[(size_t)d * OUT_C + lane] = v - mx - logf(sum);
}

// --------------- launcher ------------------------------------------------------
extern "C" void kernel_launch(void* const* d_in, const int* in_sizes, int n_in,
                              void* d_out, int out_size) {
    const float* x   = (const float*)d_in[0];
    const void*  ei  = d_in[1];
    const float* W1  = (const float*)d_in[2];
    const float* as1 = (const float*)d_in[3];
    const float* ad1 = (const float*)d_in[4];
    const float* b1  = (const float*)d_in[5];
    const float* W2  = (const float*)d_in[6];
    const float* as2 = (const float*)d_in[7];
    const float* ad2 = (const float*)d_in[8];
    const float* b2  = (const float*)d_in[9];

    int n  = in_sizes[0] / IN_C;
    int E  = in_sizes[1] / 2;
    int Et = E + n;
    int nb1024 = (n + 1023) / 1024;
    int NB1 = (n + 7) / 8;
    int NG  = (n + 127) / 128;       // gemm blocks
    int NBK = 1184;                  // bucket blocks (backfill gemm wave 2)

    prep_kernel<<<(Et + 255) / 256, 256>>>(ei, E, Et);
    scan_kernel<<<nb1024, 1024>>>(n, nb1024, Et);
    fused_kernel<<<NG + NBK, 256>>>(x, W1, as1, ad1, n, NG, Et);
    agg1_kernel<<<NB1, 256>>>(b1, W2, as2, ad2, n);
    agg2_kernel<<<NB1, 256>>>(b2, (float*)d_out, n);
}